// round 2
// baseline (speedup 1.0000x reference)
#include <cuda_runtime.h>
#include <cstdint>

#define T_SEQ 512
#define H 32
#define WPB 4   // warps per block

typedef unsigned long long u64;

__device__ __forceinline__ u64 fma2(u64 a, u64 b, u64 c) {
    u64 d;
    asm("fma.rn.f32x2 %0, %1, %2, %3;" : "=l"(d) : "l"(a), "l"(b), "l"(c));
    return d;
}
__device__ __forceinline__ u64 add2(u64 a, u64 b) {
    u64 d;
    asm("add.rn.f32x2 %0, %1, %2;" : "=l"(d) : "l"(a), "l"(b));
    return d;
}
__device__ __forceinline__ float lo_hi_sum(u64 a) {
    unsigned lo, hi;
    asm("mov.b64 {%0,%1}, %2;" : "=r"(lo), "=r"(hi) : "l"(a));
    return __uint_as_float(lo) + __uint_as_float(hi);
}
// accurate-enough fast tanh: ~1e-6 rel err, ~7 SASS instrs (MUFU.EX2 + MUFU.RCP)
__device__ __forceinline__ float tanh_fast(float x) {
    float e = __expf(-2.0f * fabsf(x));
    float r = __fdividef(1.0f - e, 1.0f + e);
    return copysignf(r, x);
}

__global__ __launch_bounds__(WPB * 32)
void rnn2_fused_kernel(const float* __restrict__ x,
                       const float* __restrict__ W_ih1, const float* __restrict__ W_hh1,
                       const float* __restrict__ b_ih1, const float* __restrict__ b_hh1,
                       const float* __restrict__ W_ih2, const float* __restrict__ W_hh2,
                       const float* __restrict__ b_ih2, const float* __restrict__ b_hh2,
                       const float* __restrict__ W_fc,  const float* __restrict__ b_fc,
                       float* __restrict__ out, int Bn)
{
    const int lane = threadIdx.x & 31;
    const int wid  = threadIdx.x >> 5;
    const int b    = blockIdx.x * WPB + wid;

    // broadcast buffers (all 16B aligned; rows are 128B so ulonglong2 reads are aligned)
    __shared__ __align__(16) float s_x [WPB][2][4][H];  // 4-timestep staging, double buffered
    __shared__ __align__(16) float s_h1[WPB][2][H];     // ping-pong by t&1
    __shared__ __align__(16) float s_h2[WPB][2][H];

    if (b >= Bn) return;

    // ---- load per-lane weight rows, packed as f32x2 pairs along j ----
    u64 wih1[16], whh1[16], wih2[16], whh2[16];
    {
        const u64* p1 = (const u64*)(W_ih1 + lane * H);
        const u64* p2 = (const u64*)(W_hh1 + lane * H);
        const u64* p3 = (const u64*)(W_ih2 + lane * H);
        const u64* p4 = (const u64*)(W_hh2 + lane * H);
        #pragma unroll
        for (int k = 0; k < 16; k++) { wih1[k] = p1[k]; whh1[k] = p2[k]; wih2[k] = p3[k]; whh2[k] = p4[k]; }
    }
    const float bias1 = b_ih1[lane] + b_hh1[lane];
    const float bias2 = b_ih2[lane] + b_hh2[lane];

    const float* xb = x + (size_t)b * T_SEQ * H;
    // x staging geometry: lane covers timestep sub = lane>>3, cols (lane&7)*4 .. +3
    const int sub = lane >> 3;
    const int col = (lane & 7) << 2;

    float h2_reg = 0.0f;
    s_h1[wid][1][lane] = 0.0f;   // h1_{-1} = 0, read by phase A at t=0 (buf (0&1)^1 = 1)

    // preload x group 0
    float4 pre = *(const float4*)(xb + sub * H + col);

    #pragma unroll 4
    for (int t = 0; t < T_SEQ; ++t) {
        const int p  = t & 1;
        const int g  = t >> 2;
        const int gb = g & 1;

        if ((t & 3) == 0) {
            // commit staged group, prefetch next (clamped; reload of last group is harmless)
            *(float4*)&s_x[wid][gb][sub][col] = pre;
            int gn = (g + 1 < T_SEQ / 4) ? (g + 1) : (T_SEQ / 4 - 1);
            pre = *(const float4*)(xb + (gn * 4 + sub) * H + col);
        }

        s_h2[wid][p][lane] = h2_reg;      // publish h2_{t-1}
        __syncwarp();

        // ---- phase A: h1_t = tanh(x_t·W_ih1^T + h1_{t-1}·W_hh1^T + bias1) ----
        const ulonglong2* xv2 = (const ulonglong2*)&s_x[wid][gb][t & 3][0];
        const ulonglong2* h1o = (const ulonglong2*)&s_h1[wid][p ^ 1][0];
        u64 accx = 0ull, acch = 0ull;
        #pragma unroll
        for (int k = 0; k < 8; k++) {
            ulonglong2 xv = xv2[k];
            ulonglong2 hv = h1o[k];
            accx = fma2(xv.x, wih1[2 * k],     accx);
            accx = fma2(xv.y, wih1[2 * k + 1], accx);
            acch = fma2(hv.x, whh1[2 * k],     acch);
            acch = fma2(hv.y, whh1[2 * k + 1], acch);
        }
        float h1n = tanh_fast(lo_hi_sum(add2(accx, acch)) + bias1);

        s_h1[wid][p][lane] = h1n;         // publish h1_t
        __syncwarp();

        // ---- phase B: h2_t = tanh(h1_t·W_ih2^T + h2_{t-1}·W_hh2^T + bias2) ----
        const ulonglong2* h1n2 = (const ulonglong2*)&s_h1[wid][p][0];
        const ulonglong2* h2o  = (const ulonglong2*)&s_h2[wid][p][0];
        u64 acca = 0ull, accb = 0ull;
        #pragma unroll
        for (int k = 0; k < 8; k++) {
            ulonglong2 av = h1n2[k];
            ulonglong2 bv = h2o[k];
            acca = fma2(av.x, wih2[2 * k],     acca);
            acca = fma2(av.y, wih2[2 * k + 1], acca);
            accb = fma2(bv.x, whh2[2 * k],     accb);
            accb = fma2(bv.y, whh2[2 * k + 1], accb);
        }
        h2_reg = tanh_fast(lo_hi_sum(add2(acca, accb)) + bias2);
    }

    // ---- final FC: out[b] = h2_T · W_fc + b_fc ----
    float v = h2_reg * W_fc[lane];
    #pragma unroll
    for (int o = 16; o; o >>= 1) v += __shfl_xor_sync(0xFFFFFFFFu, v, o);
    if (lane == 0) out[b] = v + b_fc[0];
}

extern "C" void kernel_launch(void* const* d_in, const int* in_sizes, int n_in,
                              void* d_out, int out_size)
{
    const float* x     = (const float*)d_in[0];
    const float* W_ih1 = (const float*)d_in[1];
    const float* W_hh1 = (const float*)d_in[2];
    const float* b_ih1 = (const float*)d_in[3];
    const float* b_hh1 = (const float*)d_in[4];
    const float* W_ih2 = (const float*)d_in[5];
    const float* W_hh2 = (const float*)d_in[6];
    const float* b_ih2 = (const float*)d_in[7];
    const float* b_hh2 = (const float*)d_in[8];
    const float* W_fc  = (const float*)d_in[9];
    const float* b_fc  = (const float*)d_in[10];
    float* out = (float*)d_out;

    const int Bn = in_sizes[0] / (T_SEQ * H);
    const int grid = (Bn + WPB - 1) / WPB;
    rnn2_fused_kernel<<<grid, WPB * 32>>>(x, W_ih1, W_hh1, b_ih1, b_hh1,
                                          W_ih2, W_hh2, b_ih2, b_hh2,
                                          W_fc, b_fc, out, Bn);
}